// round 6
// baseline (speedup 1.0000x reference)
#include <cuda_runtime.h>
#include <cuda_bf16.h>
#include <cstdint>

#define NN 100000
#define EE 1600000
#define DD 128
#define NBLK ((NN + 1023) / 1024)

// ---------------- scratch (device globals; no allocs allowed) ----------------
__device__ float g_msg[(size_t)NN * DD];     // mean-aggregated messages
__device__ float g_h  [(size_t)NN * DD];     // layer-0 activations
__device__ float g_h1 [(size_t)NN * 256];    // MLP hidden
__device__ int   g_rowptr[NN + 1];
__device__ int   g_colidx[EE];
__device__ int   g_hist[NN];
__device__ int   g_bsum[NBLK];
__device__ int   g_ei_is64;
// pre-transposed split-bf16 weights: Bt[c][k] = W[k][c], c in [0,128), k in [0,256)
__device__ __nv_bfloat16 g_Bt0_hi[128 * 256];
__device__ __nv_bfloat16 g_Bt0_lo[128 * 256];
__device__ __nv_bfloat16 g_Bt1_hi[128 * 256];
__device__ __nv_bfloat16 g_Bt1_lo[128 * 256];

// ---------------- helpers ----------------
__device__ __forceinline__ uint32_t smem_u32(const void* p) {
    uint32_t a;
    asm("{ .reg .u64 t; cvta.to.shared.u64 t, %1; cvt.u32.u64 %0, t; }" : "=r"(a) : "l"(p));
    return a;
}
__device__ __forceinline__ void ldsm_x4(uint32_t* r, uint32_t addr) {
    asm volatile("ldmatrix.sync.aligned.m8n8.x4.shared.b16 {%0,%1,%2,%3}, [%4];"
                 : "=r"(r[0]), "=r"(r[1]), "=r"(r[2]), "=r"(r[3]) : "r"(addr));
}
__device__ __forceinline__ void mma_bf16(float* d, const uint32_t* a, const uint32_t* b) {
    asm volatile(
        "mma.sync.aligned.m16n8k16.row.col.f32.bf16.bf16.f32 "
        "{%0,%1,%2,%3}, {%4,%5,%6,%7}, {%8,%9}, {%0,%1,%2,%3};"
        : "+f"(d[0]), "+f"(d[1]), "+f"(d[2]), "+f"(d[3])
        : "r"(a[0]), "r"(a[1]), "r"(a[2]), "r"(a[3]), "r"(b[0]), "r"(b[1]));
}

// ---------------- edge-index dtype detection ----------------
__global__ void detect_kernel(const int* __restrict__ ei_words) {
    if (threadIdx.x == 0 && blockIdx.x == 0) {
        int is64 = 1;
        for (int i = 1; i < 256; i += 2) {
            if (ei_words[i] != 0) { is64 = 0; break; }
        }
        g_ei_is64 = is64;
    }
}
__device__ __forceinline__ int load_edge(const void* ei, size_t idx) {
    if (g_ei_is64) return (int)((const long long*)ei)[idx];
    return ((const int*)ei)[idx];
}

// ---------------- CSR build ----------------
__global__ void zero_hist_kernel(int N) {
    int i = blockIdx.x * blockDim.x + threadIdx.x;
    if (i < N) g_hist[i] = 0;
}
__global__ void hist_kernel(const void* __restrict__ ei, int E) {
    int e = blockIdx.x * blockDim.x + threadIdx.x;
    if (e >= E) return;
    atomicAdd(&g_hist[load_edge(ei, (size_t)E + e)], 1);
}
__global__ __launch_bounds__(1024)
void scan1_kernel(int N) {
    __shared__ int s[1024];
    int gi = blockIdx.x * 1024 + threadIdx.x;
    int v = (gi < N) ? g_hist[gi] : 0;
    s[threadIdx.x] = v;
    __syncthreads();
    int x = v;
#pragma unroll
    for (int off = 1; off < 1024; off <<= 1) {
        int t = (threadIdx.x >= off) ? s[threadIdx.x - off] : 0;
        __syncthreads();
        x += t;
        s[threadIdx.x] = x;
        __syncthreads();
    }
    if (gi <= N) g_rowptr[gi] = x - v;
    if (threadIdx.x == 1023) g_bsum[blockIdx.x] = x;
}
__global__ void scan2_kernel(int nblk) {
    if (threadIdx.x == 0 && blockIdx.x == 0) {
        int run = 0;
        for (int b = 0; b < nblk; b++) { int t = g_bsum[b]; g_bsum[b] = run; run += t; }
    }
}
__global__ void scan3_kernel(int N, int E) {
    int i = blockIdx.x * blockDim.x + threadIdx.x;
    if (i < N) {
        g_rowptr[i] += g_bsum[i >> 10];
        g_hist[i] = 0;
    }
    if (i == 0) g_rowptr[N] = E;
}
__global__ void scatter_kernel(const void* __restrict__ ei, int E) {
    int e = blockIdx.x * blockDim.x + threadIdx.x;
    if (e >= E) return;
    int s = load_edge(ei, e);
    int d = load_edge(ei, (size_t)E + e);
    int p = g_rowptr[d] + atomicAdd(&g_hist[d], 1);
    g_colidx[p] = s;
}

// ---------------- gather aggregation: one warp per dst node ----------------
__global__ __launch_bounds__(256)
void gather_agg_kernel(const float* __restrict__ feat_in, int N) {
    const float* feat = feat_in ? feat_in : g_h;
    int node = (blockIdx.x * blockDim.x + threadIdx.x) >> 5;
    int lane = threadIdx.x & 31;
    if (node >= N) return;

    int beg = g_rowptr[node];
    int end = g_rowptr[node + 1];
    const float4* f4 = reinterpret_cast<const float4*>(feat);
    float4 acc = make_float4(0.f, 0.f, 0.f, 0.f);

    int e = beg;
    for (; e + 4 <= end; e += 4) {
        int s0 = g_colidx[e], s1 = g_colidx[e + 1], s2 = g_colidx[e + 2], s3 = g_colidx[e + 3];
        float4 a = f4[(size_t)s0 * 32 + lane];
        float4 b = f4[(size_t)s1 * 32 + lane];
        float4 c = f4[(size_t)s2 * 32 + lane];
        float4 d = f4[(size_t)s3 * 32 + lane];
        acc.x += (a.x + b.x) + (c.x + d.x);
        acc.y += (a.y + b.y) + (c.y + d.y);
        acc.z += (a.z + b.z) + (c.z + d.z);
        acc.w += (a.w + b.w) + (c.w + d.w);
    }
    for (; e < end; e++) {
        float4 a = f4[(size_t)g_colidx[e] * 32 + lane];
        acc.x += a.x; acc.y += a.y; acc.z += a.z; acc.w += a.w;
    }
    float r = 1.f / fmaxf((float)(end - beg), 1.f);
    acc.x *= r; acc.y *= r; acc.z *= r; acc.w *= r;
    reinterpret_cast<float4*>(g_msg)[(size_t)node * 32 + lane] = acc;
}

// ---------------- weight transpose + split-bf16 convert ----------------
// Bt[c][k] = (k<128 ? Wl[k][c] : Wr[k-128][c]); hi/lo split.
__global__ void tb_kernel(const float* __restrict__ Wl, const float* __restrict__ Wr,
                          __nv_bfloat16* __restrict__ bt_hi, __nv_bfloat16* __restrict__ bt_lo) {
    int c = blockIdx.x;       // 0..127
    int k = threadIdx.x;      // 0..255
    float v = (k < 128) ? Wl[k * 128 + c] : Wr[(k - 128) * 128 + c];
    __nv_bfloat16 hi = __float2bfloat16(v);
    float rem = v - __bfloat162float(hi);
    __nv_bfloat16 lo = __float2bfloat16(rem);
    bt_hi[c * 256 + k] = hi;
    bt_lo[c * 256 + k] = lo;
}

// ---------------- mma.sync split-bf16 fused SAGE GEMM ----------------
// OUT[n][c] = act( sum_k msg[n][k]*Wl[k][c] + X[n][k]*Wr[k][c] + bias[c] )
// A = [msg | X] (K=256), B = Bt (pre-transposed, [n][k]). CTA 64x128, 8 warps 4x2,
// warp tile 16x64. K chunks of 32. Split-bf16: hi*hi + hi*lo + lo*hi.
#define PAD 40   // bf16 per smem row (80B: 5x16B units, gcd(5,8)=1 -> ldmatrix conflict-free)

template <bool RELU>
__global__ __launch_bounds__(256, 2)
void sage_mma_kernel(const float* __restrict__ X_in,
                     const __nv_bfloat16* __restrict__ bt_hi,
                     const __nv_bfloat16* __restrict__ bt_lo,
                     const float* __restrict__ Bb,
                     float* __restrict__ OUT_in,
                     int N) {
    const float* X = X_in ? X_in : g_h;
    float* OUT     = OUT_in ? OUT_in : g_h;

    __shared__ __nv_bfloat16 sAhi[64 * PAD];
    __shared__ __nv_bfloat16 sAlo[64 * PAD];
    __shared__ __nv_bfloat16 sBhi[128 * PAD];
    __shared__ __nv_bfloat16 sBlo[128 * PAD];

    const int tid  = threadIdx.x;
    const int lane = tid & 31;
    const int wid  = tid >> 5;
    const int wm   = wid >> 1;      // 0..3: warp rows 16*wm
    const int wn   = wid & 1;       // 0..1: warp cols 64*wn
    const int bm   = blockIdx.x * 64;

    const uint32_t uAhi = smem_u32(sAhi);
    const uint32_t uAlo = smem_u32(sAlo);
    const uint32_t uBhi = smem_u32(sBhi);
    const uint32_t uBlo = smem_u32(sBlo);

    float acc[8][4];
#pragma unroll
    for (int i = 0; i < 8; i++)
#pragma unroll
        for (int j = 0; j < 4; j++) acc[i][j] = 0.f;

    // ldmatrix lane->address mapping (computed once)
    // A x4: row = wm*16 + ((lane>>3)&1)*8 + (lane&7), kcol = ks*16 + (lane>>4)*8
    const int a_row = wm * 16 + ((lane >> 3) & 1) * 8 + (lane & 7);
    const int a_kof = (lane >> 4) * 8;
    // B x4 (per n16 group g): n = wn*64 + g*16 + ((lane>>4)&1)*8 + (lane&7), k = ks*16 + ((lane>>3)&1)*8
    const int b_nof = ((lane >> 4) & 1) * 8 + (lane & 7);
    const int b_kof = ((lane >> 3) & 1) * 8;

    for (int chunk = 0; chunk < 8; chunk++) {
        const float* src = (chunk < 4) ? g_msg : X;
        const int kcA = (chunk & 3) * 32;
        const int kcB = chunk * 32;

        // ---- load A: 64 rows x 32 k (16 uint32 pairs per row) ----
#pragma unroll
        for (int i = 0; i < 4; i++) {
            int idx = i * 256 + tid;
            int r = idx >> 4, p = idx & 15;       // k = 2p
            int n = bm + r;
            float v0 = 0.f, v1 = 0.f;
            if (n < N) {
                float2 v = *reinterpret_cast<const float2*>(src + (size_t)n * DD + kcA + 2 * p);
                v0 = v.x; v1 = v.y;
            }
            __nv_bfloat16 h0 = __float2bfloat16(v0);
            __nv_bfloat16 h1 = __float2bfloat16(v1);
            __nv_bfloat16 l0 = __float2bfloat16(v0 - __bfloat162float(h0));
            __nv_bfloat16 l1 = __float2bfloat16(v1 - __bfloat162float(h1));
            int off = r * PAD + 2 * p;
            *reinterpret_cast<uint32_t*>(&sAhi[off]) =
                (uint32_t)__bfloat16_as_ushort(h0) | ((uint32_t)__bfloat16_as_ushort(h1) << 16);
            *reinterpret_cast<uint32_t*>(&sAlo[off]) =
                (uint32_t)__bfloat16_as_ushort(l0) | ((uint32_t)__bfloat16_as_ushort(l1) << 16);
        }
        // ---- load B: 128 rows x 32 k, hi+lo (pre-converted) ----
#pragma unroll
        for (int i = 0; i < 8; i++) {
            int idx = i * 256 + tid;
            int r = idx >> 4, p = idx & 15;
            int off = r * PAD + 2 * p;
            *reinterpret_cast<uint32_t*>(&sBhi[off]) =
                *reinterpret_cast<const uint32_t*>(bt_hi + (size_t)r * 256 + kcB + 2 * p);
            *reinterpret_cast<uint32_t*>(&sBlo[off]) =
                *reinterpret_cast<const uint32_t*>(bt_lo + (size_t)r * 256 + kcB + 2 * p);
        }
        __syncthreads();

        // ---- compute: 2 k16 steps ----
#pragma unroll
        for (int ks = 0; ks < 2; ks++) {
            uint32_t ah[4], al[4];
            uint32_t aoff = (uint32_t)((a_row * PAD + ks * 16 + a_kof) * 2);
            ldsm_x4(ah, uAhi + aoff);
            ldsm_x4(al, uAlo + aoff);
#pragma unroll
            for (int g = 0; g < 4; g++) {
                uint32_t bh[4], bl[4];
                int b_n = wn * 64 + g * 16 + b_nof;
                uint32_t boff = (uint32_t)((b_n * PAD + ks * 16 + b_kof) * 2);
                ldsm_x4(bh, uBhi + boff);
                ldsm_x4(bl, uBlo + boff);
                // n-tile 2g   -> frags {bh[0],bh[1]} / {bl[0],bl[1]}
                mma_bf16(acc[2 * g],     ah, bh);
                mma_bf16(acc[2 * g],     ah, bl);
                mma_bf16(acc[2 * g],     al, bh);
                // n-tile 2g+1 -> frags {bh[2],bh[3]} / {bl[2],bl[3]}
                mma_bf16(acc[2 * g + 1], ah, bh + 2);
                mma_bf16(acc[2 * g + 1], ah, bl + 2);
                mma_bf16(acc[2 * g + 1], al, bh + 2);
            }
        }
        __syncthreads();
    }

    // ---- epilogue ----
    const int gid = lane >> 2;
    const int qid = lane & 3;
    const int row0 = bm + wm * 16 + gid;
    const int row1 = row0 + 8;
#pragma unroll
    for (int nt = 0; nt < 8; nt++) {
        int col = wn * 64 + nt * 8 + qid * 2;
        float bx = __ldg(Bb + col);
        float by = __ldg(Bb + col + 1);
        float2 v0, v1;
        v0.x = acc[nt][0] + bx; v0.y = acc[nt][1] + by;
        v1.x = acc[nt][2] + bx; v1.y = acc[nt][3] + by;
        if (RELU) {
            v0.x = fmaxf(v0.x, 0.f); v0.y = fmaxf(v0.y, 0.f);
            v1.x = fmaxf(v1.x, 0.f); v1.y = fmaxf(v1.y, 0.f);
        }
        if (row0 < N) *reinterpret_cast<float2*>(OUT + (size_t)row0 * DD + col) = v0;
        if (row1 < N) *reinterpret_cast<float2*>(OUT + (size_t)row1 * DD + col) = v1;
    }
}

// ---------------- MLP layer 1: g_h1 = relu( relu(EMB) @ Wm1 + bm1 ) ----------------
#define M_BM 32
#define M_BK 32
__global__ __launch_bounds__(256)
void mlp1_kernel(const float* __restrict__ EMB,
                 const float* __restrict__ Wm1,
                 const float* __restrict__ bm1,
                 int N) {
    __shared__ float sA[M_BM][M_BK];
    __shared__ float sB[M_BK][256];

    const int tid = threadIdx.x;
    const int tx  = tid & 63;
    const int ty  = tid >> 6;
    const int bm  = blockIdx.x * M_BM;

    float acc[8][4];
#pragma unroll
    for (int i = 0; i < 8; i++)
#pragma unroll
        for (int j = 0; j < 4; j++) acc[i][j] = 0.f;

    for (int kc = 0; kc < DD; kc += M_BK) {
#pragma unroll
        for (int i = 0; i < 4; i++) {
            int idx = tid + i * 256;
            int r = idx >> 5, c = idx & 31;
            int n = bm + r;
            sA[r][c] = (n < N) ? fmaxf(EMB[(size_t)n * DD + kc + c], 0.f) : 0.f;
        }
#pragma unroll
        for (int i = 0; i < 32; i++) {
            int idx = tid + i * 256;
            int kk = idx >> 8, c = idx & 255;
            sB[kk][c] = Wm1[(size_t)(kc + kk) * 256 + c];
        }
        __syncthreads();

#pragma unroll
        for (int kk = 0; kk < M_BK; kk++) {
            float4 b4 = *reinterpret_cast<const float4*>(&sB[kk][tx * 4]);
#pragma unroll
            for (int i = 0; i < 8; i++) {
                float a = sA[ty * 8 + i][kk];
                acc[i][0] += a * b4.x;
                acc[i][1] += a * b4.y;
                acc[i][2] += a * b4.z;
                acc[i][3] += a * b4.w;
            }
        }
        __syncthreads();
    }

    float4 bias = *reinterpret_cast<const float4*>(&bm1[tx * 4]);
#pragma unroll
    for (int i = 0; i < 8; i++) {
        int n = bm + ty * 8 + i;
        if (n < N) {
            float4 o;
            o.x = fmaxf(acc[i][0] + bias.x, 0.f);
            o.y = fmaxf(acc[i][1] + bias.y, 0.f);
            o.z = fmaxf(acc[i][2] + bias.z, 0.f);
            o.w = fmaxf(acc[i][3] + bias.w, 0.f);
            *reinterpret_cast<float4*>(&g_h1[(size_t)n * 256 + tx * 4]) = o;
        }
    }
}

// ---------------- final projection ----------------
__global__ void pred_kernel(const float* __restrict__ Wm2,
                            const float* __restrict__ bm2,
                            float* __restrict__ PRED,
                            int N) {
    int gw   = (blockIdx.x * blockDim.x + threadIdx.x) >> 5;
    int lane = threadIdx.x & 31;
    if (gw >= N) return;
    const float4* h = reinterpret_cast<const float4*>(g_h1 + (size_t)gw * 256);
    const float4* w = reinterpret_cast<const float4*>(Wm2);
    float s = 0.f;
#pragma unroll
    for (int i = 0; i < 2; i++) {
        float4 a = h[lane + i * 32];
        float4 b = w[lane + i * 32];
        s += a.x * b.x + a.y * b.y + a.z * b.z + a.w * b.w;
    }
#pragma unroll
    for (int o = 16; o > 0; o >>= 1) s += __shfl_xor_sync(0xFFFFFFFFu, s, o);
    if (lane == 0) PRED[gw] = s + bm2[0];
}

// ---------------- launcher ----------------
extern "C" void kernel_launch(void* const* d_in, const int* in_sizes, int n_in,
                              void* d_out, int out_size) {
    const float* x   = (const float*)d_in[0];
    const void*  ei  = d_in[1];
    const float* Wl0 = (const float*)d_in[2];
    const float* b0  = (const float*)d_in[3];
    const float* Wr0 = (const float*)d_in[4];
    const float* Wl1 = (const float*)d_in[5];
    const float* b1  = (const float*)d_in[6];
    const float* Wr1 = (const float*)d_in[7];
    const float* Wm1 = (const float*)d_in[8];
    const float* bm1 = (const float*)d_in[9];
    const float* Wm2 = (const float*)d_in[10];
    const float* bm2 = (const float*)d_in[11];

    const int N = in_sizes[0] / DD;
    const int E = in_sizes[1] / 2;

    float* out  = (float*)d_out;
    float* emb  = out;
    float* pred = out + (size_t)N * DD;

    const int egrid = (E + 255) / 256;
    const int ngrid = (N + 255) / 256;
    const int nblk  = (N + 1023) / 1024;
    const int ggrid = (N + 7) / 8;
    const int tgrid = (N + 63) / 64;
    const int mgrid = (N + M_BM - 1) / M_BM;
    const int pgrid = (N + 7) / 8;

    detect_kernel<<<1, 32>>>((const int*)ei);

    // weight transpose + split-bf16 (both layers)
    tb_kernel<<<128, 256>>>(Wl0, Wr0, g_Bt0_hi, g_Bt0_lo);
    tb_kernel<<<128, 256>>>(Wl1, Wr1, g_Bt1_hi, g_Bt1_lo);

    // ---- CSR build ----
    zero_hist_kernel<<<ngrid, 256>>>(N);
    hist_kernel<<<egrid, 256>>>(ei, E);
    scan1_kernel<<<nblk, 1024>>>(N);
    scan2_kernel<<<1, 32>>>(nblk);
    scan3_kernel<<<ngrid, 256>>>(N, E);
    scatter_kernel<<<egrid, 256>>>(ei, E);

    // ---- layer 0 ----
    gather_agg_kernel<<<ggrid, 256>>>(x, N);
    sage_mma_kernel<true><<<tgrid, 256>>>(x, g_Bt0_hi, g_Bt0_lo, b0, nullptr, N);

    // ---- layer 1 (emb -> d_out) ----
    gather_agg_kernel<<<ggrid, 256>>>(nullptr, N);
    sage_mma_kernel<false><<<tgrid, 256>>>(nullptr, g_Bt1_hi, g_Bt1_lo, b1, emb, N);

    // ---- post-mp MLP ----
    mlp1_kernel<<<mgrid, 256>>>(emb, Wm1, bm1, N);
    pred_kernel<<<pgrid, 256>>>(Wm2, bm2, pred, N);
}

// round 7
// speedup vs baseline: 1.6666x; 1.6666x over previous
#include <cuda_runtime.h>
#include <cuda_bf16.h>
#include <cstdint>

#define NN 100000
#define EE 1600000
#define DD 128
#define NBLK ((NN + 1023) / 1024)

// ---------------- scratch (device globals; no allocs allowed) ----------------
__device__ float g_msg[(size_t)NN * DD];     // mean-aggregated messages
__device__ float g_h  [(size_t)NN * DD];     // layer-0 activations
__device__ float g_h1 [(size_t)NN * 256];    // MLP hidden
__device__ int   g_rowptr[NN + 1];
__device__ int   g_colidx[EE];
__device__ int   g_hist[NN];
__device__ int   g_bsum[NBLK];
__device__ int   g_ei_is64;

// ---------------- edge-index dtype detection ----------------
__global__ void detect_kernel(const int* __restrict__ ei_words) {
    if (threadIdx.x == 0 && blockIdx.x == 0) {
        int is64 = 1;
        for (int i = 1; i < 256; i += 2) {
            if (ei_words[i] != 0) { is64 = 0; break; }
        }
        g_ei_is64 = is64;
    }
}
__device__ __forceinline__ int load_edge(const void* ei, size_t idx) {
    if (g_ei_is64) return (int)((const long long*)ei)[idx];
    return ((const int*)ei)[idx];
}

// ---------------- CSR build ----------------
__global__ void zero_hist_kernel(int N) {
    int i = blockIdx.x * blockDim.x + threadIdx.x;
    if (i < N) g_hist[i] = 0;
}
__global__ void hist_kernel(const void* __restrict__ ei, int E) {
    int e = blockIdx.x * blockDim.x + threadIdx.x;
    if (e >= E) return;
    atomicAdd(&g_hist[load_edge(ei, (size_t)E + e)], 1);
}
__global__ __launch_bounds__(1024)
void scan1_kernel(int N) {
    __shared__ int s[1024];
    int gi = blockIdx.x * 1024 + threadIdx.x;
    int v = (gi < N) ? g_hist[gi] : 0;
    s[threadIdx.x] = v;
    __syncthreads();
    int x = v;
#pragma unroll
    for (int off = 1; off < 1024; off <<= 1) {
        int t = (threadIdx.x >= off) ? s[threadIdx.x - off] : 0;
        __syncthreads();
        x += t;
        s[threadIdx.x] = x;
        __syncthreads();
    }
    if (gi <= N) g_rowptr[gi] = x - v;
    if (threadIdx.x == 1023) g_bsum[blockIdx.x] = x;
}
__global__ void scan2_kernel(int nblk) {
    if (threadIdx.x == 0 && blockIdx.x == 0) {
        int run = 0;
        for (int b = 0; b < nblk; b++) { int t = g_bsum[b]; g_bsum[b] = run; run += t; }
    }
}
__global__ void scan3_kernel(int N, int E) {
    int i = blockIdx.x * blockDim.x + threadIdx.x;
    if (i < N) {
        g_rowptr[i] += g_bsum[i >> 10];
        g_hist[i] = 0;
    }
    if (i == 0) g_rowptr[N] = E;
}
__global__ void scatter_kernel(const void* __restrict__ ei, int E) {
    int e = blockIdx.x * blockDim.x + threadIdx.x;
    if (e >= E) return;
    int s = load_edge(ei, e);
    int d = load_edge(ei, (size_t)E + e);
    int p = g_rowptr[d] + atomicAdd(&g_hist[d], 1);
    g_colidx[p] = s;
}

// ---------------- gather aggregation: one warp per dst node ----------------
__global__ __launch_bounds__(256)
void gather_agg_kernel(const float* __restrict__ feat_in, int N) {
    const float* feat = feat_in ? feat_in : g_h;
    int node = (blockIdx.x * blockDim.x + threadIdx.x) >> 5;
    int lane = threadIdx.x & 31;
    if (node >= N) return;

    int beg = g_rowptr[node];
    int end = g_rowptr[node + 1];
    const float4* f4 = reinterpret_cast<const float4*>(feat);
    float4 acc = make_float4(0.f, 0.f, 0.f, 0.f);

    int e = beg;
    for (; e + 4 <= end; e += 4) {
        int s0 = g_colidx[e], s1 = g_colidx[e + 1], s2 = g_colidx[e + 2], s3 = g_colidx[e + 3];
        float4 a = f4[(size_t)s0 * 32 + lane];
        float4 b = f4[(size_t)s1 * 32 + lane];
        float4 c = f4[(size_t)s2 * 32 + lane];
        float4 d = f4[(size_t)s3 * 32 + lane];
        acc.x += (a.x + b.x) + (c.x + d.x);
        acc.y += (a.y + b.y) + (c.y + d.y);
        acc.z += (a.z + b.z) + (c.z + d.z);
        acc.w += (a.w + b.w) + (c.w + d.w);
    }
    for (; e < end; e++) {
        float4 a = f4[(size_t)g_colidx[e] * 32 + lane];
        acc.x += a.x; acc.y += a.y; acc.z += a.z; acc.w += a.w;
    }
    float r = 1.f / fmaxf((float)(end - beg), 1.f);
    acc.x *= r; acc.y *= r; acc.z *= r; acc.w *= r;
    reinterpret_cast<float4*>(g_msg)[(size_t)node * 32 + lane] = acc;
}

// ---------------- fused SAGE layer GEMM (8x8 register tiles) ----------------
// OUT[n][c] = act( sum_k g_msg[n][k]*Wl[k][c] + X[n][k]*Wr[k][c] + bias[c] )
// CTA tile 128x128, 256 threads as 16x16, thread tile 8 rows x (4+4) cols.
#define S_BM 128
#define S_BK 16
#define APAD 17   // A smem row stride (floats)

template <bool RELU>
__global__ __launch_bounds__(256)
void sage_kernel(const float* __restrict__ X_in,
                 const float* __restrict__ Wl,
                 const float* __restrict__ Wr,
                 const float* __restrict__ B,
                 float* __restrict__ OUT_in,
                 int N) {
    const float* X = X_in ? X_in : g_h;
    float* OUT     = OUT_in ? OUT_in : g_h;

    __shared__ float sAm[S_BM][APAD];
    __shared__ float sAx[S_BM][APAD];
    __shared__ float sBl[S_BK][128];
    __shared__ float sBr[S_BK][128];

    const int tid = threadIdx.x;
    const int tx  = tid & 15;          // col group
    const int ty  = tid >> 4;          // row group (rows ty*8..+7)
    const int bm  = blockIdx.x * S_BM;

    float acc[8][8];
#pragma unroll
    for (int i = 0; i < 8; i++)
#pragma unroll
        for (int j = 0; j < 8; j++) acc[i][j] = 0.f;

    for (int kc = 0; kc < DD; kc += S_BK) {
        // A tiles: 128 rows x 16 cols per source, float4 gmem loads (2 per thread per src)
#pragma unroll
        for (int i = 0; i < 2; i++) {
            int idx = i * 256 + tid;
            int r = idx >> 2, q = (idx & 3) * 4;
            int n = bm + r;
            float4 vm = make_float4(0.f, 0.f, 0.f, 0.f);
            float4 vx = vm;
            if (n < N) {
                vm = *reinterpret_cast<const float4*>(g_msg + (size_t)n * DD + kc + q);
                vx = *reinterpret_cast<const float4*>(X + (size_t)n * DD + kc + q);
            }
            sAm[r][q + 0] = vm.x; sAm[r][q + 1] = vm.y; sAm[r][q + 2] = vm.z; sAm[r][q + 3] = vm.w;
            sAx[r][q + 0] = vx.x; sAx[r][q + 1] = vx.y; sAx[r][q + 2] = vx.z; sAx[r][q + 3] = vx.w;
        }
        // B tiles: 16 x 128 per matrix, float4 loads (2 per thread per matrix)
#pragma unroll
        for (int i = 0; i < 2; i++) {
            int idx = i * 256 + tid;
            int k = idx >> 5, c = (idx & 31) * 4;
            *reinterpret_cast<float4*>(&sBl[k][c]) =
                *reinterpret_cast<const float4*>(Wl + (size_t)(kc + k) * 128 + c);
            *reinterpret_cast<float4*>(&sBr[k][c]) =
                *reinterpret_cast<const float4*>(Wr + (size_t)(kc + k) * 128 + c);
        }
        __syncthreads();

#pragma unroll
        for (int kk = 0; kk < S_BK; kk++) {
            float am[8], ax[8];
#pragma unroll
            for (int i = 0; i < 8; i++) {
                am[i] = sAm[ty * 8 + i][kk];
                ax[i] = sAx[ty * 8 + i][kk];
            }
            float4 bl0 = *reinterpret_cast<const float4*>(&sBl[kk][tx * 4]);
            float4 bl1 = *reinterpret_cast<const float4*>(&sBl[kk][64 + tx * 4]);
            float4 br0 = *reinterpret_cast<const float4*>(&sBr[kk][tx * 4]);
            float4 br1 = *reinterpret_cast<const float4*>(&sBr[kk][64 + tx * 4]);
#pragma unroll
            for (int i = 0; i < 8; i++) {
                acc[i][0] += am[i] * bl0.x + ax[i] * br0.x;
                acc[i][1] += am[i] * bl0.y + ax[i] * br0.y;
                acc[i][2] += am[i] * bl0.z + ax[i] * br0.z;
                acc[i][3] += am[i] * bl0.w + ax[i] * br0.w;
                acc[i][4] += am[i] * bl1.x + ax[i] * br1.x;
                acc[i][5] += am[i] * bl1.y + ax[i] * br1.y;
                acc[i][6] += am[i] * bl1.z + ax[i] * br1.z;
                acc[i][7] += am[i] * bl1.w + ax[i] * br1.w;
            }
        }
        __syncthreads();
    }

    // epilogue: cols tx*4 and 64+tx*4
    float4 b0 = *reinterpret_cast<const float4*>(B + tx * 4);
    float4 b1 = *reinterpret_cast<const float4*>(B + 64 + tx * 4);
#pragma unroll
    for (int i = 0; i < 8; i++) {
        int n = bm + ty * 8 + i;
        if (n < N) {
            float4 o0, o1;
            o0.x = acc[i][0] + b0.x; o0.y = acc[i][1] + b0.y;
            o0.z = acc[i][2] + b0.z; o0.w = acc[i][3] + b0.w;
            o1.x = acc[i][4] + b1.x; o1.y = acc[i][5] + b1.y;
            o1.z = acc[i][6] + b1.z; o1.w = acc[i][7] + b1.w;
            if (RELU) {
                o0.x = fmaxf(o0.x, 0.f); o0.y = fmaxf(o0.y, 0.f);
                o0.z = fmaxf(o0.z, 0.f); o0.w = fmaxf(o0.w, 0.f);
                o1.x = fmaxf(o1.x, 0.f); o1.y = fmaxf(o1.y, 0.f);
                o1.z = fmaxf(o1.z, 0.f); o1.w = fmaxf(o1.w, 0.f);
            }
            *reinterpret_cast<float4*>(OUT + (size_t)n * DD + tx * 4) = o0;
            *reinterpret_cast<float4*>(OUT + (size_t)n * DD + 64 + tx * 4) = o1;
        }
    }
}

// ---------------- MLP layer 1 (8x8 register tiles) ----------------
// g_h1 = relu( relu(EMB) @ Wm1 + bm1 ).  CTA tile 64x256, 256 threads as 32x8.
#define M_BM 64
#define M_BK 16

__global__ __launch_bounds__(256)
void mlp1_kernel(const float* __restrict__ EMB,
                 const float* __restrict__ Wm1,
                 const float* __restrict__ bm1,
                 int N) {
    __shared__ float sA[M_BM][APAD];
    __shared__ float sB[M_BK][256];

    const int tid = threadIdx.x;
    const int tx  = tid & 31;          // col group: cols tx*4 and 128+tx*4
    const int ty  = tid >> 5;          // row group: rows ty*8..+7
    const int bm  = blockIdx.x * M_BM;

    float acc[8][8];
#pragma unroll
    for (int i = 0; i < 8; i++)
#pragma unroll
        for (int j = 0; j < 8; j++) acc[i][j] = 0.f;

    for (int kc = 0; kc < DD; kc += M_BK) {
        // A: 64x16 floats = 1024 -> 1 float4/thread, relu applied at load
        {
            int r = tid >> 2, q = (tid & 3) * 4;
            int n = bm + r;
            float4 v = make_float4(0.f, 0.f, 0.f, 0.f);
            if (n < N)
                v = *reinterpret_cast<const float4*>(EMB + (size_t)n * DD + kc + q);
            sA[r][q + 0] = fmaxf(v.x, 0.f);
            sA[r][q + 1] = fmaxf(v.y, 0.f);
            sA[r][q + 2] = fmaxf(v.z, 0.f);
            sA[r][q + 3] = fmaxf(v.w, 0.f);
        }
        // B: 16x256 = 4096 floats -> 4 float4/thread
#pragma unroll
        for (int i = 0; i < 4; i++) {
            int idx = i * 256 + tid;
            int k = idx >> 6, c = (idx & 63) * 4;
            *reinterpret_cast<float4*>(&sB[k][c]) =
                *reinterpret_cast<const float4*>(Wm1 + (size_t)(kc + k) * 256 + c);
        }
        __syncthreads();

#pragma unroll
        for (int kk = 0; kk < M_BK; kk++) {
            float a[8];
#pragma unroll
            for (int i = 0; i < 8; i++) a[i] = sA[ty * 8 + i][kk];
            float4 w0 = *reinterpret_cast<const float4*>(&sB[kk][tx * 4]);
            float4 w1 = *reinterpret_cast<const float4*>(&sB[kk][128 + tx * 4]);
#pragma unroll
            for (int i = 0; i < 8; i++) {
                acc[i][0] += a[i] * w0.x;
                acc[i][1] += a[i] * w0.y;
                acc[i][2] += a[i] * w0.z;
                acc[i][3] += a[i] * w0.w;
                acc[i][4] += a[i] * w1.x;
                acc[i][5] += a[i] * w1.y;
                acc[i][6] += a[i] * w1.z;
                acc[i][7] += a[i] * w1.w;
            }
        }
        __syncthreads();
    }

    float4 b0 = *reinterpret_cast<const float4*>(bm1 + tx * 4);
    float4 b1 = *reinterpret_cast<const float4*>(bm1 + 128 + tx * 4);
#pragma unroll
    for (int i = 0; i < 8; i++) {
        int n = bm + ty * 8 + i;
        if (n < N) {
            float4 o0, o1;
            o0.x = fmaxf(acc[i][0] + b0.x, 0.f);
            o0.y = fmaxf(acc[i][1] + b0.y, 0.f);
            o0.z = fmaxf(acc[i][2] + b0.z, 0.f);
            o0.w = fmaxf(acc[i][3] + b0.w, 0.f);
            o1.x = fmaxf(acc[i][4] + b1.x, 0.f);
            o1.y = fmaxf(acc[i][5] + b1.y, 0.f);
            o1.z = fmaxf(acc[i][6] + b1.z, 0.f);
            o1.w = fmaxf(acc[i][7] + b1.w, 0.f);
            *reinterpret_cast<float4*>(&g_h1[(size_t)n * 256 + tx * 4]) = o0;
            *reinterpret_cast<float4*>(&g_h1[(size_t)n * 256 + 128 + tx * 4]) = o1;
        }
    }
}

// ---------------- final projection ----------------
__global__ void pred_kernel(const float* __restrict__ Wm2,
                            const float* __restrict__ bm2,
                            float* __restrict__ PRED,
                            int N) {
    int gw   = (blockIdx.x * blockDim.x + threadIdx.x) >> 5;
    int lane = threadIdx.x & 31;
    if (gw >= N) return;
    const float4* h = reinterpret_cast<const float4*>(g_h1 + (size_t)gw * 256);
    const float4* w = reinterpret_cast<const float4*>(Wm2);
    float s = 0.f;
#pragma unroll
    for (int i = 0; i < 2; i++) {
        float4 a = h[lane + i * 32];
        float4 b = w[lane + i * 32];
        s += a.x * b.x + a.y * b.y + a.z * b.z + a.w * b.w;
    }
#pragma unroll
    for (int o = 16; o > 0; o >>= 1) s += __shfl_xor_sync(0xFFFFFFFFu, s, o);
    if (lane == 0) PRED[gw] = s + bm2[0];
}

// ---------------- launcher ----------------
extern "C" void kernel_launch(void* const* d_in, const int* in_sizes, int n_in,
                              void* d_out, int out_size) {
    const float* x   = (const float*)d_in[0];
    const void*  ei  = d_in[1];
    const float* Wl0 = (const float*)d_in[2];
    const float* b0  = (const float*)d_in[3];
    const float* Wr0 = (const float*)d_in[4];
    const float* Wl1 = (const float*)d_in[5];
    const float* b1  = (const float*)d_in[6];
    const float* Wr1 = (const float*)d_in[7];
    const float* Wm1 = (const float*)d_in[8];
    const float* bm1 = (const float*)d_in[9];
    const float* Wm2 = (const float*)d_in[10];
    const float* bm2 = (const float*)d_in[11];

    const int N = in_sizes[0] / DD;
    const int E = in_sizes[1] / 2;

    float* out  = (float*)d_out;
    float* emb  = out;
    float* pred = out + (size_t)N * DD;

    const int egrid = (E + 255) / 256;
    const int ngrid = (N + 255) / 256;
    const int nblk  = (N + 1023) / 1024;
    const int ggrid = (N + 7) / 8;
    const int sgrid = (N + S_BM - 1) / S_BM;
    const int mgrid = (N + M_BM - 1) / M_BM;
    const int pgrid = (N + 7) / 8;

    detect_kernel<<<1, 32>>>((const int*)ei);

    // ---- CSR build (once; reused by both layers) ----
    zero_hist_kernel<<<ngrid, 256>>>(N);
    hist_kernel<<<egrid, 256>>>(ei, E);
    scan1_kernel<<<nblk, 1024>>>(N);
    scan2_kernel<<<1, 32>>>(nblk);
    scan3_kernel<<<ngrid, 256>>>(N, E);
    scatter_kernel<<<egrid, 256>>>(ei, E);

    // ---- layer 0 ----
    gather_agg_kernel<<<ggrid, 256>>>(x, N);
    sage_kernel<true><<<sgrid, 256>>>(x, Wl0, Wr0, b0, nullptr, N);   // OUT -> g_h

    // ---- layer 1 (emb -> d_out) ----
    gather_agg_kernel<<<ggrid, 256>>>(nullptr, N);
    sage_kernel<false><<<sgrid, 256>>>(nullptr, Wl1, Wr1, b1, emb, N);

    // ---- post-mp MLP ----
    mlp1_kernel<<<mgrid, 256>>>(emb, Wm1, bm1, N);
    pred_kernel<<<pgrid, 256>>>(Wm2, bm2, pred, N);
}